// round 13
// baseline (speedup 1.0000x reference)
#include <cuda_runtime.h>

// LIF scan — fused chain + overlapped block replay, v3 (fine-grained).
// B=16, S=256, H=128, N=64.  T = S*H = 32768 steps per (b,n) chain.
//
// R13 changes vs R12 (200.4us):
//  1. BLKROWS 8 -> 4: 64 checkpoints/chain, 2048 output CTAs of 512 steps.
//     Halves the post-chain tail and starts output draining earlier.
//  2. Chain warp prefetches x at register depth 2 (~80 cyc slack) so LDS
//     latency under flusher LSU contention can never stall the chain.
//  3. Natural smem footprint again (48KB occupancy cap was neutral).
//
// Step math (bit-identical to reference order; validated rel_err 0.0 in
// R4/R6/R7/R8/R9/R12):
//   m = (v <= thr) ? 1.0f : 0.0f   (FSET)
//   v = fmaf(v, m, x)              (fma(v,1,x)==fl(v+x); fma(v,0,x)==x)
//   out = (v > thr) ? v : 0.0f     (off-chain)

#define BB 16
#define SS 256
#define HH 128
#define NN 64
#define TT (SS * HH)

#define BLKROWS 4
#define NBLK (SS / BLKROWS)           // 64
#define ROWPAD 132
#define NGRP 32                       // (b, neuron-half)
#define NCHAIN NGRP
#define CHUNKS (BLKROWS * (HH / 4))   // 128 float4 per 4-row block

static const size_t BSNH = (size_t)BB * SS * NN * HH;

__device__ float g_chk[NBLK][BB][NN];
__device__ int   g_flag[NBLK][NGRP][32];   // per-lane flags

__device__ __forceinline__ float set_le(float a, float b) {
    float r; asm("set.le.f32.f32 %0, %1, %2;" : "=f"(r) : "f"(a), "f"(b)); return r;
}
__device__ __forceinline__ void st_release(int* p, int v) {
    asm volatile("st.release.gpu.global.b32 [%0], %1;" :: "l"(p), "r"(v) : "memory");
}
__device__ __forceinline__ int ld_acquire(const int* p) {
    int v; asm volatile("ld.acquire.gpu.global.b32 %0, [%1];" : "=r"(v) : "l"(p) : "memory");
    return v;
}

#define CHAIN_STEP(XC) do {                 \
    float _m = set_le(v, thr);              \
    v = __fmaf_rn(v, _m, (XC));             \
} while (0)

#define OUT_STEP(XC, OC) do {               \
    float _m = set_le(v, thr);              \
    v = __fmaf_rn(v, _m, (XC));             \
    (OC) = (v > thr) ? v : 0.0f;            \
} while (0)

__global__ void lif_reset()
{
    int i = blockIdx.x * blockDim.x + threadIdx.x;
    if (i < NBLK * NGRP * 32) ((int*)g_flag)[i] = 0;
}

__global__ void __launch_bounds__(64, 1)
lif_fused(const float* __restrict__ x,       // [B, S, H]
          const float* __restrict__ thresh,  // [N]
          const float* __restrict__ acc0,    // [B, N]
          float* __restrict__ outbuf,        // outs | spikes
          int write_spikes)
{
    // Union of both roles' needs: output staging (2*32*ROWPAD floats) is
    // the larger; chain role uses it as the x double buffer (+2 f4 pad).
    __shared__ float smem_raw[2 * 32 * ROWPAD];

    const int tid  = threadIdx.x;
    const int lane = tid & 31;

    if (blockIdx.x < NCHAIN) {
        // ================== CHAIN CTA ==================
        const int grp  = blockIdx.x;
        const int b    = grp >> 1;
        const int half = grp & 1;
        const int wid  = tid >> 5;

        // Two x blocks of BLKROWS rows (+ 8 floats pad for depth-2 overread).
        float (*xsh)[BLKROWS * HH + 8] = (float (*)[BLKROWS * HH + 8])smem_raw;
        const float4* __restrict__ xg = (const float4*)(x + (size_t)b * TT);

        if (wid == 1) {                       // preload block 0
            #pragma unroll
            for (int i = lane; i < CHUNKS; i += 32)
                ((float4*)xsh[0])[i] = xg[i];
        }
        __syncthreads();

        if (wid == 0) {
            const int n = half * 32 + lane;
            const float thr = thresh[n];
            float v = acc0[b * NN + n];

            for (int blk = 0; blk < NBLK; ++blk) {
                // Publish checkpoint (plain store + per-lane release flag).
                g_chk[blk][b][n] = v;
                st_release(&g_flag[blk][grp][lane], 1);

                const float4* xs4 = (const float4*)xsh[blk & 1];
                float4 xv = xs4[0];
                float4 xn = xs4[1];
                #pragma unroll 8
                for (int q = 0; q < CHUNKS; ++q) {
                    float4 x2 = xs4[q + 2];   // depth-2 prefetch (pad-covered)
                    CHAIN_STEP(xv.x); CHAIN_STEP(xv.y);
                    CHAIN_STEP(xv.z); CHAIN_STEP(xv.w);
                    xv = xn; xn = x2;
                }
                __syncthreads();              // block consumed; next staged
            }
        } else {
            for (int blk = 0; blk < NBLK; ++blk) {
                if (blk + 1 < NBLK) {
                    const float4* src = xg + (size_t)(blk + 1) * CHUNKS;
                    float4* dst = (float4*)xsh[(blk + 1) & 1];
                    #pragma unroll
                    for (int i = lane; i < CHUNKS; i += 32)
                        dst[i] = src[i];
                }
                __syncthreads();
            }
        }
    } else {
        // ================== OUTPUT CTA ==================
        const int cidx = blockIdx.x - NCHAIN;
        const int grp  = cidx & (NGRP - 1);   // grp varies fastest
        const int sblk = cidx >> 5;           // low (early) blocks first
        const int b    = grp >> 1;
        const int n0   = (grp & 1) * 32;
        const int s0   = sblk * BLKROWS;

        float (*sbuf)[32 * ROWPAD] = (float (*)[32 * ROWPAD])smem_raw;

        if (tid < 32) {
            // -------- producer: per-lane acquire, then exact replay ------
            const int n = n0 + lane;
            while (ld_acquire(&g_flag[sblk][grp][lane]) == 0)
                __nanosleep(64);

            const float thr = thresh[n];
            float v = g_chk[sblk][b][n];

            const float4* __restrict__ xp =
                (const float4*)(x + (size_t)b * TT + (size_t)s0 * HH);

            float* const row0 = &sbuf[0][lane * ROWPAD];
            float* const row1 = &sbuf[1][lane * ROWPAD];

            for (int r = 0; r < BLKROWS; ++r) {
                float* rw = (r & 1) ? row1 : row0;
                const float4* xrow = xp + r * (HH / 4);
                #pragma unroll 8
                for (int q = 0; q < HH / 4; ++q) {
                    float4 xv = xrow[q];      // broadcast LDG (L2-hot)
                    float4 o;
                    OUT_STEP(xv.x, o.x); OUT_STEP(xv.y, o.y);
                    OUT_STEP(xv.z, o.z); OUT_STEP(xv.w, o.w);
                    *(float4*)&rw[q * 4] = o;
                }
                __syncthreads();              // row r staged
            }
        } else {
            // -------- flusher: transpose + spikes --------
            const int fl = tid - 32;
            float* __restrict__ outp = outbuf;
            float* __restrict__ spkp = outbuf + BSNH;

            for (int r = 0; r < BLKROWS; ++r) {
                __syncthreads();              // wait for row r
                const float* buf = sbuf[r & 1];
                const int s = s0 + r;
                size_t base = (((size_t)b * SS + s) * NN + n0) * HH + fl * 4;
                #pragma unroll 4
                for (int rr = 0; rr < 32; ++rr) {
                    float4 vv = *(const float4*)&buf[rr * ROWPAD + fl * 4];
                    *(float4*)&outp[base + (size_t)rr * HH] = vv;
                    if (write_spikes) {
                        float4 sp;
                        sp.x = (vv.x > 0.0f) ? 1.0f : 0.0f;
                        sp.y = (vv.y > 0.0f) ? 1.0f : 0.0f;
                        sp.z = (vv.z > 0.0f) ? 1.0f : 0.0f;
                        sp.w = (vv.w > 0.0f) ? 1.0f : 0.0f;
                        *(float4*)&spkp[base + (size_t)rr * HH] = sp;
                    }
                }
            }
        }
    }
}

extern "C" void kernel_launch(void* const* d_in, const int* in_sizes, int n_in,
                              void* d_out, int out_size)
{
    const float* x      = (const float*)d_in[0];  // [16, 256, 128] f32
    const float* thresh = (const float*)d_in[1];  // [64] f32
    const float* acc0   = (const float*)d_in[2];  // [16, 64] f32
    float* out = (float*)d_out;

    int write_spikes = ((size_t)out_size >= 2 * BSNH) ? 1 : 0;

    lif_reset<<<64, 1024>>>();
    lif_fused<<<NCHAIN + NGRP * NBLK, 64>>>(x, thresh, acc0, out, write_spikes);
}

// round 14
// speedup vs baseline: 1.1549x; 1.1549x over previous
#include <cuda_runtime.h>

// LIF scan — fused chain + overlapped block replay, v4.
// B=16, S=256, H=128, N=64.  T = S*H = 32768 steps per (b,n) chain.
//
// R14 changes vs R12 (200.4us):
//  1. Chain warp no longer touches global memory per block: it hands the
//     checkpoint through shared memory (one STS); the loader warp performs
//     the STG + st.release publication. Removes ~32 L2-round-trip stalls
//     from the chain's critical path.
//  2. Final 8 rows split into 4 x 2-row sub-blocks with direct checkpoint
//     publication -> post-chain tail is a 256-step replay (~2.5us) instead
//     of 1024 (~10us). Chain skips its own last 256 steps (unconsumed).
//  3. No reset kernel: each flag's single consumer resets it after the
//     acquire (stream-ordered replays preserve the invariant; first launch
//     uses static zero-init).
//
// Step math (bit-identical to reference order; rel_err 0.0 in
// R4/R6/R7/R8/R9/R12/R13):
//   m = (v <= thr) ? 1.0f : 0.0f   (FSET)
//   v = fmaf(v, m, x)              (fma(v,1,x)==fl(v+x); fma(v,0,x)==x)
//   out = (v > thr) ? v : 0.0f     (off-chain)

#define BB 16
#define SS 256
#define HH 128
#define NN 64
#define TT (SS * HH)

#define BLKROWS 8
#define NXBLK (SS / BLKROWS)          // 32 x-buffer blocks
#define REGBLK 31                     // regular 8-row output blocks (rows 0..247)
#define TAILSUB 4                     // 2-row sub-blocks (rows 248..255)
#define TAILROWS 2
#define NSLOT (REGBLK + TAILSUB)      // 35 checkpoint slots (slot 0 unused)
#define ROWPAD 132
#define NGRP 32                       // (b, neuron-half)
#define NCHAIN NGRP
#define CHUNKS (BLKROWS * (HH / 4))   // 256 float4 per 8-row block
#define TCHUNKS (TAILROWS * (HH / 4)) // 64 float4 per 2-row sub-block

static const size_t BSNH = (size_t)BB * SS * NN * HH;

__device__ float g_chk[NSLOT][BB][NN];
__device__ int   g_flag[NSLOT][NGRP][32];   // per-lane flags, zero-init

__device__ __forceinline__ float set_le(float a, float b) {
    float r; asm("set.le.f32.f32 %0, %1, %2;" : "=f"(r) : "f"(a), "f"(b)); return r;
}
__device__ __forceinline__ void st_release(int* p, int v) {
    asm volatile("st.release.gpu.global.b32 [%0], %1;" :: "l"(p), "r"(v) : "memory");
}
__device__ __forceinline__ int ld_acquire(const int* p) {
    int v; asm volatile("ld.acquire.gpu.global.b32 %0, [%1];" : "=r"(v) : "l"(p) : "memory");
    return v;
}

#define CHAIN_STEP(XC) do {                 \
    float _m = set_le(v, thr);              \
    v = __fmaf_rn(v, _m, (XC));             \
} while (0)

#define OUT_STEP(XC, OC) do {               \
    float _m = set_le(v, thr);              \
    v = __fmaf_rn(v, _m, (XC));             \
    (OC) = (v > thr) ? v : 0.0f;            \
} while (0)

__global__ void __launch_bounds__(64, 1)
lif_fused(const float* __restrict__ x,       // [B, S, H]
          const float* __restrict__ thresh,  // [N]
          const float* __restrict__ acc0,    // [B, N]
          float* __restrict__ outbuf,        // outs | spikes
          int write_spikes)
{
    // Union of both roles' needs (output staging is the larger).
    __shared__ float smem_raw[2 * 32 * ROWPAD];
    __shared__ float chkbuf[2][32];          // chain -> loader handoff

    const int tid  = threadIdx.x;
    const int lane = tid & 31;

    if (blockIdx.x < NCHAIN) {
        // ================== CHAIN CTA ==================
        const int grp  = blockIdx.x;
        const int b    = grp >> 1;
        const int half = grp & 1;
        const int wid  = tid >> 5;
        const int n    = half * 32 + lane;

        float (*xsh)[BLKROWS * HH + 4] = (float (*)[BLKROWS * HH + 4])smem_raw;
        const float4* __restrict__ xg = (const float4*)(x + (size_t)b * TT);

        if (wid == 1) {                       // preload x block 0
            #pragma unroll
            for (int i = lane; i < CHUNKS; i += 32)
                ((float4*)xsh[0])[i] = xg[i];
        }
        __syncthreads();

        if (wid == 0) {
            // -------- chain warp: pure compute + STS handoff --------
            const float thr = thresh[n];
            float v = acc0[b * NN + n];

            for (int blk = 0; blk < REGBLK; ++blk) {   // blocks 0..30
                const float4* xs4 = (const float4*)xsh[blk & 1];
                float4 xv = xs4[0];
                #pragma unroll 8
                for (int q = 0; q < CHUNKS; ++q) {
                    float4 xn = xs4[q + 1];   // broadcast LDS, pad-covered
                    CHAIN_STEP(xv.x); CHAIN_STEP(xv.y);
                    CHAIN_STEP(xv.z); CHAIN_STEP(xv.w);
                    xv = xn;
                }
                chkbuf[(blk + 1) & 1][lane] = v;   // state entering blk+1
                __syncthreads();              // block consumed; next staged
            }

            // -------- tail: rows 248..255 as 4 x 2-row sub-blocks --------
            // v = state entering row 248; x block 31 sits in xsh[1].
            const float4* xs4 = (const float4*)xsh[1];
            #pragma unroll
            for (int sub = 0; sub < TAILSUB; ++sub) {
                g_chk[REGBLK + sub][b][n] = v;        // direct publish
                st_release(&g_flag[REGBLK + sub][grp][lane], 1);
                if (sub == TAILSUB - 1) break;        // last segment unused
                const float4* xt = xs4 + sub * TCHUNKS;
                #pragma unroll 8
                for (int q = 0; q < TCHUNKS; ++q) {
                    float4 xv = xt[q];
                    CHAIN_STEP(xv.x); CHAIN_STEP(xv.y);
                    CHAIN_STEP(xv.z); CHAIN_STEP(xv.w);
                }
            }
        } else {
            // -------- loader warp: prefetch + checkpoint publication -----
            for (int blk = 0; blk < REGBLK; ++blk) {   // 31 iterations
                if (blk >= 1) {
                    // publish state entering block blk (written by chain
                    // before the sync that ended block blk-1)
                    float val = chkbuf[blk & 1][lane];
                    g_chk[blk][b][n] = val;
                    st_release(&g_flag[blk][grp][lane], 1);
                }
                if (blk + 1 < NXBLK) {        // prefetch x block blk+1
                    const float4* src = xg + (size_t)(blk + 1) * CHUNKS;
                    float4* dst = (float4*)xsh[(blk + 1) & 1];
                    #pragma unroll
                    for (int i = lane; i < CHUNKS; i += 32)
                        dst[i] = src[i];
                }
                __syncthreads();
            }
        }
    } else {
        // ================== OUTPUT CTA ==================
        const int cidx = blockIdx.x - NCHAIN;
        const int grp  = cidx & (NGRP - 1);   // grp varies fastest
        const int idx  = cidx >> 5;           // 0..34, early blocks first
        const int b    = grp >> 1;
        const int n0   = (grp & 1) * 32;

        int s0, nrows, slot;
        if (idx == 0)            { s0 = 0;                nrows = BLKROWS;  slot = -1;  }
        else if (idx < REGBLK)   { s0 = idx * BLKROWS;    nrows = BLKROWS;  slot = idx; }
        else { int sub = idx - REGBLK;
               s0 = REGBLK * BLKROWS + sub * TAILROWS;    nrows = TAILROWS; slot = REGBLK + sub; }

        float (*sbuf)[32 * ROWPAD] = (float (*)[32 * ROWPAD])smem_raw;

        if (tid < 32) {
            // -------- producer: acquire checkpoint, exact replay ---------
            const int n = n0 + lane;
            const float thr = thresh[n];
            float v;
            if (slot < 0) {
                v = acc0[b * NN + n];          // block 0: true initial state
            } else {
                while (ld_acquire(&g_flag[slot][grp][lane]) == 0)
                    __nanosleep(64);
                g_flag[slot][grp][lane] = 0;   // self-reset for next replay
                v = g_chk[slot][b][n];
            }

            const float4* __restrict__ xp =
                (const float4*)(x + (size_t)b * TT + (size_t)s0 * HH);

            float* const row0 = &sbuf[0][lane * ROWPAD];
            float* const row1 = &sbuf[1][lane * ROWPAD];

            for (int r = 0; r < nrows; ++r) {
                float* rw = (r & 1) ? row1 : row0;
                const float4* xrow = xp + r * (HH / 4);
                #pragma unroll 8
                for (int q = 0; q < HH / 4; ++q) {
                    float4 xv = xrow[q];       // broadcast LDG (L2-hot)
                    float4 o;
                    OUT_STEP(xv.x, o.x); OUT_STEP(xv.y, o.y);
                    OUT_STEP(xv.z, o.z); OUT_STEP(xv.w, o.w);
                    *(float4*)&rw[q * 4] = o;
                }
                __syncthreads();               // row r staged
            }
        } else {
            // -------- flusher: transpose + spikes --------
            const int fl = tid - 32;
            float* __restrict__ outp = outbuf;
            float* __restrict__ spkp = outbuf + BSNH;

            for (int r = 0; r < nrows; ++r) {
                __syncthreads();               // wait for row r
                const float* buf = sbuf[r & 1];
                const int s = s0 + r;
                size_t base = (((size_t)b * SS + s) * NN + n0) * HH + fl * 4;
                #pragma unroll 4
                for (int rr = 0; rr < 32; ++rr) {
                    float4 vv = *(const float4*)&buf[rr * ROWPAD + fl * 4];
                    *(float4*)&outp[base + (size_t)rr * HH] = vv;
                    if (write_spikes) {
                        float4 sp;
                        sp.x = (vv.x > 0.0f) ? 1.0f : 0.0f;
                        sp.y = (vv.y > 0.0f) ? 1.0f : 0.0f;
                        sp.z = (vv.z > 0.0f) ? 1.0f : 0.0f;
                        sp.w = (vv.w > 0.0f) ? 1.0f : 0.0f;
                        *(float4*)&spkp[base + (size_t)rr * HH] = sp;
                    }
                }
            }
        }
    }
}

extern "C" void kernel_launch(void* const* d_in, const int* in_sizes, int n_in,
                              void* d_out, int out_size)
{
    const float* x      = (const float*)d_in[0];  // [16, 256, 128] f32
    const float* thresh = (const float*)d_in[1];  // [64] f32
    const float* acc0   = (const float*)d_in[2];  // [16, 64] f32
    float* out = (float*)d_out;

    int write_spikes = ((size_t)out_size >= 2 * BSNH) ? 1 : 0;

    lif_fused<<<NCHAIN + NGRP * NSLOT, 64>>>(x, thresh, acc0, out, write_spikes);
}

// round 15
// speedup vs baseline: 1.1715x; 1.0143x over previous
#include <cuda_runtime.h>

// LIF scan — fused chain + overlapped block replay, v5 (2-step merge chain).
// B=16, S=256, H=128, N=64.  T = S*H = 32768 steps per (b,n) chain.
//
// R15 change vs R14 (181.0us): the chain warp advances TWO steps per
// dependency round trip. Over a pair (x0, x1):
//   W  = (x0<=thr) ? fl(x0+x1) : x1          (restart path; x-only, off-chain)
//   a  = v + x0                              (survive partial sum, fma 4)
//   u  = fma(a, FSET(a<=thr), x1)            (survive-path second step)
//   v' = fma(u, FSET(v<=thr), W*FSET(v>thr)) (exact one-hot merge, fma 4)
// Critical path 18 cyc / 2 steps = 9 cyc/step vs 10 for the per-step
// FSET->FFMA form (cross-pipe 5+5 every step).
// Exact: masks are {0,1}; fma(u,1,+-0)=u; fma(u,0,W)=W; fma(a,1,x)=fl(a+x);
// fma(a,0,x)=x. Identical value sequence to the reference order.
//
// Structure (R14, proven): 32 chain CTAs publish checkpoints via the loader
// warp (smem handoff, no global ops on the chain warp); final 8 rows split
// into 2-row sub-blocks to shrink the tail; per-lane release/acquire flags,
// consumer-reset (no reset kernel); 1120 output CTAs replay blocks from
// exact checkpoints with smem-transpose coalesced stores.

#define BB 16
#define SS 256
#define HH 128
#define NN 64
#define TT (SS * HH)

#define BLKROWS 8
#define NXBLK (SS / BLKROWS)          // 32 x-buffer blocks
#define REGBLK 31                     // regular 8-row output blocks
#define TAILSUB 4                     // 2-row sub-blocks (rows 248..255)
#define TAILROWS 2
#define NSLOT (REGBLK + TAILSUB)      // 35 checkpoint slots
#define ROWPAD 132
#define NGRP 32
#define NCHAIN NGRP
#define CHUNKS (BLKROWS * (HH / 4))   // 256 float4 per 8-row block
#define TCHUNKS (TAILROWS * (HH / 4)) // 64 float4 per 2-row sub-block

static const size_t BSNH = (size_t)BB * SS * NN * HH;

__device__ float g_chk[NSLOT][BB][NN];
__device__ int   g_flag[NSLOT][NGRP][32];   // per-lane flags, zero-init

__device__ __forceinline__ float set_le(float a, float b) {
    float r; asm("set.le.f32.f32 %0, %1, %2;" : "=f"(r) : "f"(a), "f"(b)); return r;
}
__device__ __forceinline__ float set_gt(float a, float b) {
    float r; asm("set.gt.f32.f32 %0, %1, %2;" : "=f"(r) : "f"(a), "f"(b)); return r;
}
__device__ __forceinline__ void st_release(int* p, int v) {
    asm volatile("st.release.gpu.global.b32 [%0], %1;" :: "l"(p), "r"(v) : "memory");
}
__device__ __forceinline__ int ld_acquire(const int* p) {
    int v; asm volatile("ld.acquire.gpu.global.b32 %0, [%1];" : "=r"(v) : "l"(p) : "memory");
    return v;
}

// Single exact step (tail segments only).
#define CHAIN_STEP(XC) do {                 \
    float _m = set_le(v, thr);              \
    v = __fmaf_rn(v, _m, (XC));             \
} while (0)

// Exact 2-step merge: 18-cyc critical path for two steps.
#define PAIR_STEP(X0, X1) do {              \
    float _q  = set_le((X0), thr);          \
    float _W  = __fmaf_rn((X0), _q, (X1));  \
    float _m0 = set_le(v, thr);             \
    float _n0 = set_gt(v, thr);             \
    float _a  = v + (X0);                   \
    float _ma = set_le(_a, thr);            \
    float _u  = __fmaf_rn(_a, _ma, (X1));   \
    float _W2 = _W * _n0;                   \
    v = __fmaf_rn(_u, _m0, _W2);            \
} while (0)

// Output-phase step (throughput-parallel; latency irrelevant).
#define OUT_STEP(XC, OC) do {               \
    float _m = set_le(v, thr);              \
    v = __fmaf_rn(v, _m, (XC));             \
    (OC) = (v > thr) ? v : 0.0f;            \
} while (0)

__global__ void __launch_bounds__(64, 1)
lif_fused(const float* __restrict__ x,       // [B, S, H]
          const float* __restrict__ thresh,  // [N]
          const float* __restrict__ acc0,    // [B, N]
          float* __restrict__ outbuf,        // outs | spikes
          int write_spikes)
{
    __shared__ float smem_raw[2 * 32 * ROWPAD];
    __shared__ float chkbuf[2][32];          // chain -> loader handoff

    const int tid  = threadIdx.x;
    const int lane = tid & 31;

    if (blockIdx.x < NCHAIN) {
        // ================== CHAIN CTA ==================
        const int grp  = blockIdx.x;
        const int b    = grp >> 1;
        const int half = grp & 1;
        const int wid  = tid >> 5;
        const int n    = half * 32 + lane;

        float (*xsh)[BLKROWS * HH + 4] = (float (*)[BLKROWS * HH + 4])smem_raw;
        const float4* __restrict__ xg = (const float4*)(x + (size_t)b * TT);

        if (wid == 1) {                       // preload x block 0
            #pragma unroll
            for (int i = lane; i < CHUNKS; i += 32)
                ((float4*)xsh[0])[i] = xg[i];
        }
        __syncthreads();

        if (wid == 0) {
            // -------- chain warp: 2-step merge recurrence --------
            const float thr = thresh[n];
            float v = acc0[b * NN + n];

            for (int blk = 0; blk < REGBLK; ++blk) {   // blocks 0..30
                const float4* xs4 = (const float4*)xsh[blk & 1];
                float4 xv = xs4[0];
                #pragma unroll 8
                for (int q = 0; q < CHUNKS; ++q) {
                    float4 xn = xs4[q + 1];   // broadcast LDS, pad-covered
                    PAIR_STEP(xv.x, xv.y);
                    PAIR_STEP(xv.z, xv.w);
                    xv = xn;
                }
                chkbuf[(blk + 1) & 1][lane] = v;   // state entering blk+1
                __syncthreads();              // block consumed; next staged
            }

            // -------- tail: rows 248..255 as 4 x 2-row sub-blocks --------
            const float4* xs4 = (const float4*)xsh[1];
            #pragma unroll
            for (int sub = 0; sub < TAILSUB; ++sub) {
                g_chk[REGBLK + sub][b][n] = v;        // direct publish
                st_release(&g_flag[REGBLK + sub][grp][lane], 1);
                if (sub == TAILSUB - 1) break;        // last segment unused
                const float4* xt = xs4 + sub * TCHUNKS;
                #pragma unroll 8
                for (int q = 0; q < TCHUNKS; ++q) {
                    float4 xv = xt[q];
                    PAIR_STEP(xv.x, xv.y);
                    PAIR_STEP(xv.z, xv.w);
                }
            }
        } else {
            // -------- loader warp: prefetch + checkpoint publication -----
            for (int blk = 0; blk < REGBLK; ++blk) {
                if (blk >= 1) {
                    float val = chkbuf[blk & 1][lane];
                    g_chk[blk][b][n] = val;
                    st_release(&g_flag[blk][grp][lane], 1);
                }
                if (blk + 1 < NXBLK) {        // prefetch x block blk+1
                    const float4* src = xg + (size_t)(blk + 1) * CHUNKS;
                    float4* dst = (float4*)xsh[(blk + 1) & 1];
                    #pragma unroll
                    for (int i = lane; i < CHUNKS; i += 32)
                        dst[i] = src[i];
                }
                __syncthreads();
            }
        }
    } else {
        // ================== OUTPUT CTA ==================
        const int cidx = blockIdx.x - NCHAIN;
        const int grp  = cidx & (NGRP - 1);
        const int idx  = cidx >> 5;           // 0..34, early blocks first
        const int b    = grp >> 1;
        const int n0   = (grp & 1) * 32;

        int s0, nrows, slot;
        if (idx == 0)            { s0 = 0;                nrows = BLKROWS;  slot = -1;  }
        else if (idx < REGBLK)   { s0 = idx * BLKROWS;    nrows = BLKROWS;  slot = idx; }
        else { int sub = idx - REGBLK;
               s0 = REGBLK * BLKROWS + sub * TAILROWS;    nrows = TAILROWS; slot = REGBLK + sub; }

        float (*sbuf)[32 * ROWPAD] = (float (*)[32 * ROWPAD])smem_raw;

        if (tid < 32) {
            // -------- producer: acquire checkpoint, exact replay ---------
            const int n = n0 + lane;
            const float thr = thresh[n];
            float v;
            if (slot < 0) {
                v = acc0[b * NN + n];
            } else {
                while (ld_acquire(&g_flag[slot][grp][lane]) == 0)
                    __nanosleep(64);
                g_flag[slot][grp][lane] = 0;   // self-reset for next replay
                v = g_chk[slot][b][n];
            }

            const float4* __restrict__ xp =
                (const float4*)(x + (size_t)b * TT + (size_t)s0 * HH);

            float* const row0 = &sbuf[0][lane * ROWPAD];
            float* const row1 = &sbuf[1][lane * ROWPAD];

            for (int r = 0; r < nrows; ++r) {
                float* rw = (r & 1) ? row1 : row0;
                const float4* xrow = xp + r * (HH / 4);
                #pragma unroll 8
                for (int q = 0; q < HH / 4; ++q) {
                    float4 xv = xrow[q];       // broadcast LDG (L2-hot)
                    float4 o;
                    OUT_STEP(xv.x, o.x); OUT_STEP(xv.y, o.y);
                    OUT_STEP(xv.z, o.z); OUT_STEP(xv.w, o.w);
                    *(float4*)&rw[q * 4] = o;
                }
                __syncthreads();               // row r staged
            }
        } else {
            // -------- flusher: transpose + spikes --------
            const int fl = tid - 32;
            float* __restrict__ outp = outbuf;
            float* __restrict__ spkp = outbuf + BSNH;

            for (int r = 0; r < nrows; ++r) {
                __syncthreads();               // wait for row r
                const float* buf = sbuf[r & 1];
                const int s = s0 + r;
                size_t base = (((size_t)b * SS + s) * NN + n0) * HH + fl * 4;
                #pragma unroll 4
                for (int rr = 0; rr < 32; ++rr) {
                    float4 vv = *(const float4*)&buf[rr * ROWPAD + fl * 4];
                    *(float4*)&outp[base + (size_t)rr * HH] = vv;
                    if (write_spikes) {
                        float4 sp;
                        sp.x = (vv.x > 0.0f) ? 1.0f : 0.0f;
                        sp.y = (vv.y > 0.0f) ? 1.0f : 0.0f;
                        sp.z = (vv.z > 0.0f) ? 1.0f : 0.0f;
                        sp.w = (vv.w > 0.0f) ? 1.0f : 0.0f;
                        *(float4*)&spkp[base + (size_t)rr * HH] = sp;
                    }
                }
            }
        }
    }
}

extern "C" void kernel_launch(void* const* d_in, const int* in_sizes, int n_in,
                              void* d_out, int out_size)
{
    const float* x      = (const float*)d_in[0];  // [16, 256, 128] f32
    const float* thresh = (const float*)d_in[1];  // [64] f32
    const float* acc0   = (const float*)d_in[2];  // [16, 64] f32
    float* out = (float*)d_out;

    int write_spikes = ((size_t)out_size >= 2 * BSNH) ? 1 : 0;

    lif_fused<<<NCHAIN + NGRP * NSLOT, 64>>>(x, thresh, acc0, out, write_spikes);
}